// round 5
// baseline (speedup 1.0000x reference)
#include <cuda_runtime.h>
#include <math.h>

// YoloV1Loss_5136780886770
// outputs:   (16384, 7, 7, 30) f32  = 96.3 MB streamed once  -> HBM-bound
// gt_boxes:  (16384, 8, 4)     f32  (49 cells/image reuse -> L1)
// gt_labels: (16384, 8)        i32
// out: scalar f32 = sum(per_cell)/16384

#define NCELLS (16384 * 49)
#define BLK 128
#define NBLOCKS (NCELLS / BLK)   // 6272 exactly, no tail
#define FBLK 256                 // finalize block size

// Per-block partial sums: plain stores, deterministic fixed-order reduction in
// the finalize kernel. No atomics, no cross-replay state.
__device__ double g_part[NBLOCKS];

__global__ void __launch_bounds__(BLK) yolo_loss_kernel(
    const float* __restrict__ outputs,
    const float* __restrict__ gt_boxes,
    const int*   __restrict__ gt_labels)
{
    // Transposed stage: sm[c*128 + r], c in [0,30), r = cell-in-block.
    // Read phase: sm[c*128 + tid] is lane-linear -> conflict-free, no padding.
    __shared__ float sm[30 * BLK];
    __shared__ float wsum[BLK / 32];

    const int base = blockIdx.x * BLK;

    // Vectorized staging: 128 cells * 30 f32 = 960 float4 (16B-aligned:
    // block base byte offset = blockIdx * 15360, multiple of 16).
    {
        const float4* gsrc = (const float4*)(outputs + (size_t)base * 30);
        #pragma unroll
        for (int v = threadIdx.x; v < 960; v += BLK) {
            float4 q = gsrc[v];                  // LDG.128, fully coalesced
            int e = v * 4;                       // element index
            int r = e / 30;
            int c = e - r * 30;
            // 4 consecutive elements may straddle a row boundary (30 % 4 != 0)
            sm[c * BLK + r] = q.x;
            if (++c == 30) { c = 0; ++r; }
            sm[c * BLK + r] = q.y;
            if (++c == 30) { c = 0; ++r; }
            sm[c * BLK + r] = q.z;
            if (++c == 30) { c = 0; ++r; }
            sm[c * BLK + r] = q.w;
        }
    }
    __syncthreads();

    const int t    = threadIdx.x;
    const int cell = base + t;
    const int img  = cell / 49;

    // channel accessor: conflict-free column read
    #define CH(c) sm[(c) * BLK + t]

    // ---- predicted boxes (B=2) ----
    float x1[2], y1[2], x2[2], y2[2], area[2], conf[2];
    float px[2], py[2], pw[2], ph[2];
    #pragma unroll
    for (int b = 0; b < 2; b++) {
        px[b] = CH(b*5+0); py[b] = CH(b*5+1);
        pw[b] = CH(b*5+2); ph[b] = CH(b*5+3);
        conf[b] = CH(b*5+4);
        x1[b] = px[b] - 0.5f * pw[b];  x2[b] = px[b] + 0.5f * pw[b];
        y1[b] = py[b] - 0.5f * ph[b];  y2[b] = py[b] + 0.5f * ph[b];
        area[b] = pw[b] * ph[b];
    }

    // ---- pairwise IoU vs 8 GT; first-occurrence argmax of max-over-b ----
    const float* gb = gt_boxes + (size_t)img * 32;
    float best_iou = -1.0f;
    float iou0_at_j = 0.0f, iou1_at_j = 0.0f;

    #pragma unroll
    for (int n = 0; n < 8; n++) {
        float4 g = __ldg((const float4*)(gb + n * 4));
        float gx1 = g.x - 0.5f * g.z, gx2 = g.x + 0.5f * g.z;
        float gy1 = g.y - 0.5f * g.w, gy2 = g.y + 0.5f * g.w;
        float ga  = g.z * g.w;

        float iou_b[2];
        #pragma unroll
        for (int b = 0; b < 2; b++) {
            float iw = fmaxf(fminf(x2[b], gx2) - fmaxf(x1[b], gx1), 0.0f);
            float ih = fmaxf(fminf(y2[b], gy2) - fmaxf(y1[b], gy1), 0.0f);
            float inter = iw * ih;
            iou_b[b] = inter / (area[b] + ga - inter + 1e-6f);
        }
        float m = fmaxf(iou_b[0], iou_b[1]);
        if (m > best_iou) {              // strict > == jnp.argmax first-occurrence
            best_iou = m;
            iou0_at_j = iou_b[0];
            iou1_at_j = iou_b[1];
        }
    }

    // best_b: argmax over B at j_star (tie -> 0)
    const int bb = (iou1_at_j > iou0_at_j) ? 1 : 0;

    // Faithful to reference: gt_sel indexes the N axis with best_b:
    // gt_sel = gt_boxes[img, bb]
    float4 gs = __ldg((const float4*)(gb + bb * 4));

    float dx = px[bb] - gs.x;
    float dy = py[bb] - gs.y;
    float dw = sqrtf(pw[bb]) - sqrtf(gs.z);
    float dh = sqrtf(ph[bb]) - sqrtf(gs.w);
    float loc = 5.0f * (dx*dx + dy*dy + dw*dw + dh*dh);

    float dconf = conf[bb] - best_iou;
    float conf_obj = dconf * dconf;

    // ---- cross-entropy: lse(cls) - mean_n cls[label_n] ----
    float cls[20];
    #pragma unroll
    for (int c = 0; c < 20; c++) cls[c] = CH(10 + c);

    float mx = cls[0];
    #pragma unroll
    for (int c = 1; c < 20; c++) mx = fmaxf(mx, cls[c]);
    float se = 0.0f;
    #pragma unroll
    for (int c = 0; c < 20; c++) se += __expf(cls[c] - mx);
    float lse = mx + __logf(se);

    const int* gl = gt_labels + (size_t)img * 8;
    float acc = 0.0f;
    #pragma unroll
    for (int n = 0; n < 8; n++) acc += cls[__ldg(gl + n)];
    float ce = lse - acc * 0.125f;

    float noobj = 0.5f * (conf[0]*conf[0] + conf[1]*conf[1]);

    float val = (best_iou > 0.0f) ? (loc + conf_obj + ce) : noobj;

    // ---- reduction: warp shuffle -> smem -> one plain store per block ----
    #pragma unroll
    for (int o = 16; o > 0; o >>= 1)
        val += __shfl_down_sync(0xffffffffu, val, o);
    if ((t & 31) == 0) wsum[t >> 5] = val;
    __syncthreads();
    if (t == 0) {
        double s = (double)wsum[0] + (double)wsum[1]
                 + (double)wsum[2] + (double)wsum[3];
        g_part[blockIdx.x] = s;          // deterministic, no atomic
    }
    #undef CH
}

// Deterministic fixed-order reduction of the 6272 partials; writes out.
__global__ void __launch_bounds__(FBLK) yolo_final_kernel(float* out) {
    __shared__ double sd[FBLK];
    const int t = threadIdx.x;

    double s = 0.0;
    for (int i = t; i < NBLOCKS; i += FBLK)   // fixed index order per thread
        s += g_part[i];
    sd[t] = s;
    __syncthreads();

    #pragma unroll
    for (int o = FBLK / 2; o > 0; o >>= 1) {  // fixed-order tree
        if (t < o) sd[t] += sd[t + o];
        __syncthreads();
    }
    if (t == 0)
        out[0] = (float)(sd[0] * (1.0 / 16384.0));
}

extern "C" void kernel_launch(void* const* d_in, const int* in_sizes, int n_in,
                              void* d_out, int out_size)
{
    const float* outputs   = (const float*)d_in[0];
    const float* gt_boxes  = (const float*)d_in[1];
    const int*   gt_labels = (const int*)  d_in[2];
    float* out = (float*)d_out;

    yolo_loss_kernel<<<NBLOCKS, BLK>>>(outputs, gt_boxes, gt_labels);
    yolo_final_kernel<<<1, FBLK>>>(out);
}

// round 6
// speedup vs baseline: 1.2103x; 1.2103x over previous
#include <cuda_runtime.h>
#include <math.h>

// YoloV1Loss_5136780886770
// outputs:   (16384, 7, 7, 30) f32  = 96.3 MB streamed once  -> HBM floor ~15-18us
// gt_boxes:  (16384, 8, 4)     f32  (49 cells/image reuse -> L1)
// gt_labels: (16384, 8)        i32
// out: scalar f32 = sum(per_cell)/16384

#define NCELLS (16384 * 49)
#define BLK 256
#define NBLOCKS (NCELLS / BLK)   // 3136 exactly, no tail

__device__ double   g_part[NBLOCKS];
__device__ unsigned g_count = 0;   // returns to 0 every completed run (replay-safe)

__global__ void __launch_bounds__(BLK) yolo_loss_kernel(
    const float* __restrict__ outputs,
    const float* __restrict__ gt_boxes,
    const int*   __restrict__ gt_labels,
    float*       __restrict__ out)
{
    // Padded row-major stage: sm[r*31 + c]. 31 coprime 32 =>
    //   writes (address-consecutive) conflict-free, reads (stride 31) conflict-free.
    __shared__ float  sm[BLK * 31];
    __shared__ float  wsum[BLK / 32];
    __shared__ bool   is_last;

    const int t    = threadIdx.x;
    const int base = blockIdx.x * BLK;

    // ---- staging: 256 cells * 30 f32 = 1920 float4, LDG.128 coalesced ----
    {
        const float4* gsrc = (const float4*)(outputs + (size_t)base * 30);
        for (int v = t; v < (BLK * 30) / 4; v += BLK) {
            float4 q = gsrc[v];
            int e = v * 4;
            int r = e / 30;
            int c = e - r * 30;
            int addr = r * 31 + c;
            float vals[4] = {q.x, q.y, q.z, q.w};
            #pragma unroll
            for (int k = 0; k < 4; k++) {
                sm[addr] = vals[k];
                if (++c == 30) { c = 0; addr += 2; } else { addr += 1; }
            }
        }
    }
    __syncthreads();

    const float* p   = sm + t * 31;          // this thread's 30 channels
    const int   cell = base + t;
    const int   img  = cell / 49;

    // ---- predicted boxes (B=2) ----
    float x1[2], y1[2], x2[2], y2[2], area[2], conf[2];
    float px[2], py[2], pw[2], ph[2];
    #pragma unroll
    for (int b = 0; b < 2; b++) {
        px[b] = p[b*5+0]; py[b] = p[b*5+1];
        pw[b] = p[b*5+2]; ph[b] = p[b*5+3];
        conf[b] = p[b*5+4];
        x1[b] = px[b] - 0.5f * pw[b];  x2[b] = px[b] + 0.5f * pw[b];
        y1[b] = py[b] - 0.5f * ph[b];  y2[b] = py[b] + 0.5f * ph[b];
        area[b] = pw[b] * ph[b];
    }

    // ---- IoU argmax via rational (inter, union+eps) cross-multiplication ----
    // iou = i/u with u > 0 always; a/b > c/d  <=>  a*d > c*b.
    const float* gb = gt_boxes + (size_t)img * 32;

    float best_i = 0.0f, best_u = 1.0f;      // overwritten by n=0 unconditionally
    float i0_j = 0.0f, u0_j = 1.0f, i1_j = 0.0f, u1_j = 1.0f;

    #pragma unroll
    for (int n = 0; n < 8; n++) {
        float4 g = __ldg((const float4*)(gb + n * 4));
        float gx1 = g.x - 0.5f * g.z, gx2 = g.x + 0.5f * g.z;
        float gy1 = g.y - 0.5f * g.w, gy2 = g.y + 0.5f * g.w;
        float ga  = g.z * g.w;

        float iv[2], uv[2];
        #pragma unroll
        for (int b = 0; b < 2; b++) {
            float iw = fmaxf(fminf(x2[b], gx2) - fmaxf(x1[b], gx1), 0.0f);
            float ih = fmaxf(fminf(y2[b], gy2) - fmaxf(y1[b], gy1), 0.0f);
            float inter = iw * ih;
            iv[b] = inter;
            uv[b] = area[b] + ga - inter + 1e-6f;
        }
        // max over b (fmaxf(iou0, iou1)): pick larger rational
        bool  s1  = (iv[1] * uv[0] > iv[0] * uv[1]);
        float m_i = s1 ? iv[1] : iv[0];
        float m_u = s1 ? uv[1] : uv[0];
        // running argmax over n, strict > == first occurrence
        if (n == 0 || (m_i * best_u > best_i * m_u)) {
            best_i = m_i;  best_u = m_u;
            i0_j = iv[0];  u0_j = uv[0];
            i1_j = iv[1];  u1_j = uv[1];
        }
    }

    // best_b at j_star: argmax over B, tie -> 0
    const int bb = (i1_j * u0_j > i0_j * u1_j) ? 1 : 0;

    // One real division: identical operands/op to the reference's iou value.
    const float best_iou = best_i / best_u;

    // Faithful to reference quirk: gt_sel = gt_boxes[img, best_b]
    float4 gs = __ldg((const float4*)(gb + bb * 4));

    float dx = px[bb] - gs.x;
    float dy = py[bb] - gs.y;
    float dw = sqrtf(pw[bb]) - sqrtf(gs.z);
    float dh = sqrtf(ph[bb]) - sqrtf(gs.w);
    float loc = 5.0f * (dx*dx + dy*dy + dw*dw + dh*dh);

    float dconf = conf[bb] - best_iou;
    float conf_obj = dconf * dconf;

    // ---- cross-entropy straight from smem (no register-array spill) ----
    float mx = p[10];
    #pragma unroll
    for (int c = 11; c < 30; c++) mx = fmaxf(mx, p[c]);
    float se = 0.0f;
    #pragma unroll
    for (int c = 10; c < 30; c++) se += __expf(p[c] - mx);
    float lse = mx + __logf(se);

    const int* gl = gt_labels + (size_t)img * 8;
    float acc = 0.0f;
    #pragma unroll
    for (int n = 0; n < 8; n++) acc += p[10 + __ldg(gl + n)];   // LDS, dynamic
    float ce = lse - acc * 0.125f;

    float noobj = 0.5f * (conf[0]*conf[0] + conf[1]*conf[1]);

    float val = (best_i > 0.0f) ? (loc + conf_obj + ce) : noobj;

    // ---- block reduction -> partial store ----
    #pragma unroll
    for (int o = 16; o > 0; o >>= 1)
        val += __shfl_down_sync(0xffffffffu, val, o);
    if ((t & 31) == 0) wsum[t >> 5] = val;
    __syncthreads();
    if (t == 0) {
        double s = 0.0;
        #pragma unroll
        for (int w = 0; w < BLK / 32; w++) s += (double)wsum[w];
        g_part[blockIdx.x] = s;
        __threadfence();
        unsigned c = atomicAdd(&g_count, 1u);
        is_last = (c == (unsigned)(gridDim.x - 1));
    }
    __syncthreads();

    // ---- last block: deterministic fixed-order final reduction ----
    if (is_last) {
        __threadfence();                      // see all g_part stores
        __shared__ double sd[BLK];
        double s = 0.0;
        for (int i = t; i < NBLOCKS; i += BLK)   // fixed index order
            s += g_part[i];
        sd[t] = s;
        __syncthreads();
        #pragma unroll
        for (int o = BLK / 2; o > 0; o >>= 1) {  // fixed-order tree
            if (t < o) sd[t] += sd[t + o];
            __syncthreads();
        }
        if (t == 0) {
            out[0] = (float)(sd[0] * (1.0 / 16384.0));
            g_count = 0;                      // reset for next replay
        }
    }
}

extern "C" void kernel_launch(void* const* d_in, const int* in_sizes, int n_in,
                              void* d_out, int out_size)
{
    const float* outputs   = (const float*)d_in[0];
    const float* gt_boxes  = (const float*)d_in[1];
    const int*   gt_labels = (const int*)  d_in[2];
    float* out = (float*)d_out;

    yolo_loss_kernel<<<NBLOCKS, BLK>>>(outputs, gt_boxes, gt_labels, out);
}

// round 9
// speedup vs baseline: 1.7023x; 1.4065x over previous
#include <cuda_runtime.h>
#include <math.h>

// YoloV1Loss_5136780886770
// outputs:   (16384, 7, 7, 30) f32  = 96.3 MB streamed once
// gt_boxes:  (16384, 8, 4)     f32  (49 cells/image reuse -> L1)
// gt_labels: (16384, 8)        i32
// out: scalar f32 = sum(per_cell)/16384
//
// R6 ncu: issue=50%, ALU=31%, L1=41%, DRAM=26% -> instruction/latency bound.
// R7/R8: linear smem (STS.128 staging, LDS.64 reads, channels in registers),
// minimal argmax carry set (best_i, best_u, s1-bit), smem class gather,
// fused deterministic finalize in the last-arriving block.

#define NCELLS (16384 * 49)
#define BLK 256
#define NBLOCKS (NCELLS / BLK)   // 3136 exactly, no tail
#define NVEC ((BLK * 30) / 4)    // 1920 float4 per block

__device__ double   g_part[NBLOCKS];
__device__ unsigned g_count = 0;   // returns to 0 every completed run (replay-safe)

__global__ void __launch_bounds__(BLK) yolo_loss_kernel(
    const float* __restrict__ outputs,
    const float* __restrict__ gt_boxes,
    const int*   __restrict__ gt_labels,
    float*       __restrict__ out)
{
    // Linear stage: sm[r*30 + c]. Writes are raw float4 copies (no math);
    // reads are LDS.64 (word-stride 30/lane -> conflict-free per phase).
    __shared__ float sm[BLK * 30];
    __shared__ float wsum[BLK / 32];
    __shared__ bool  is_last;

    const int t    = threadIdx.x;
    const int base = blockIdx.x * BLK;

    // ---- staging: pure LDG.128 -> STS.128, no address arithmetic ----
    {
        const float4* gsrc = (const float4*)(outputs + (size_t)base * 30);
        float4* sm4 = (float4*)sm;
        #pragma unroll
        for (int k = 0; k < 8; k++) {
            int v = t + k * BLK;
            if (v < NVEC) sm4[v] = gsrc[v];   // k=7 half-predicated (1920 = 7.5*256)
        }
    }
    __syncthreads();

    // ---- per-thread channels -> registers via 15 LDS.64 ----
    float ch[30];
    {
        const float2* p2 = (const float2*)(sm + t * 30);   // 120B base, 8B-aligned
        #pragma unroll
        for (int i = 0; i < 15; i++) {
            float2 q = p2[i];
            ch[2*i]   = q.x;
            ch[2*i+1] = q.y;
        }
    }

    const int cell = base + t;
    const int img  = cell / 49;

    // ---- predicted boxes (B=2) ----
    float x1[2], y1[2], x2[2], y2[2], area[2], conf[2];
    #pragma unroll
    for (int b = 0; b < 2; b++) {
        float cx = ch[b*5+0], cy = ch[b*5+1], w = ch[b*5+2], h = ch[b*5+3];
        conf[b] = ch[b*5+4];
        x1[b] = cx - 0.5f * w;  x2[b] = cx + 0.5f * w;
        y1[b] = cy - 0.5f * h;  y2[b] = cy + 0.5f * h;
        area[b] = w * h;
    }

    // ---- IoU argmax via rational (inter, union+eps) cross-multiplication ----
    // iou = i/u, u > 0 always; a/b > c/d  <=>  a*d > c*b.
    // Carry only (best_i, best_u, best_s1): bb at j_star equals the b-select
    // bit s1 of the winning n (tie semantics preserved: both strict >).
    const float* gb = gt_boxes + (size_t)img * 32;

    float best_i = 0.0f, best_u = 1.0f;      // overwritten at n=0 unconditionally
    bool  best_s1 = false;

    #pragma unroll
    for (int n = 0; n < 8; n++) {
        float4 g = __ldg((const float4*)(gb + n * 4));
        float gx1 = g.x - 0.5f * g.z, gx2 = g.x + 0.5f * g.z;
        float gy1 = g.y - 0.5f * g.w, gy2 = g.y + 0.5f * g.w;
        float ga  = g.z * g.w;

        float iv[2], uv[2];
        #pragma unroll
        for (int b = 0; b < 2; b++) {
            float iw = fmaxf(fminf(x2[b], gx2) - fmaxf(x1[b], gx1), 0.0f);
            float ih = fmaxf(fminf(y2[b], gy2) - fmaxf(y1[b], gy1), 0.0f);
            float inter = iw * ih;
            iv[b] = inter;
            uv[b] = area[b] + ga - inter + 1e-6f;
        }
        // max over b (== fmaxf(iou0, iou1)): larger rational; tie -> b=0
        bool  s1  = (iv[1] * uv[0] > iv[0] * uv[1]);
        float m_i = s1 ? iv[1] : iv[0];
        float m_u = s1 ? uv[1] : uv[0];
        // running argmax over n, strict > == first occurrence
        if (n == 0 || (m_i * best_u > best_i * m_u)) {
            best_i = m_i;  best_u = m_u;  best_s1 = s1;
        }
    }

    const int bb = best_s1 ? 1 : 0;

    // One real division: identical operands/op to the reference's iou value.
    const float best_iou = best_i / best_u;

    // Faithful to reference quirk: gt_sel = gt_boxes[img, best_b]
    float4 gs = __ldg((const float4*)(gb + bb * 4));

    float psx = best_s1 ? ch[5] : ch[0];
    float psy = best_s1 ? ch[6] : ch[1];
    float psw = best_s1 ? ch[7] : ch[2];
    float psh = best_s1 ? ch[8] : ch[3];

    float dx = psx - gs.x;
    float dy = psy - gs.y;
    float dw = sqrtf(psw) - sqrtf(gs.z);
    float dh = sqrtf(psh) - sqrtf(gs.w);
    float loc = 5.0f * (dx*dx + dy*dy + dw*dw + dh*dh);

    float dconf = (best_s1 ? conf[1] : conf[0]) - best_iou;
    float conf_obj = dconf * dconf;

    // ---- cross-entropy: lse(cls) - mean_n cls[label_n] ----
    float mx = ch[10];
    #pragma unroll
    for (int c = 11; c < 30; c++) mx = fmaxf(mx, ch[c]);
    float se = 0.0f;
    #pragma unroll
    for (int c = 10; c < 30; c++) se += __expf(ch[c] - mx);
    float lse = mx + __logf(se);

    // dynamic gather from smem (registers would spill to local memory)
    const int* gl = gt_labels + (size_t)img * 8;
    const float* cls_sm = sm + t * 30 + 10;
    float acc = 0.0f;
    #pragma unroll
    for (int n = 0; n < 8; n++) acc += cls_sm[__ldg(gl + n)];
    float ce = lse - acc * 0.125f;

    float noobj = 0.5f * (conf[0]*conf[0] + conf[1]*conf[1]);

    float val = (best_i > 0.0f) ? (loc + conf_obj + ce) : noobj;

    // ---- block reduction -> partial store ----
    #pragma unroll
    for (int o = 16; o > 0; o >>= 1)
        val += __shfl_down_sync(0xffffffffu, val, o);
    if ((t & 31) == 0) wsum[t >> 5] = val;
    __syncthreads();
    if (t == 0) {
        double s = 0.0;
        #pragma unroll
        for (int w = 0; w < BLK / 32; w++) s += (double)wsum[w];
        g_part[blockIdx.x] = s;
        __threadfence();
        unsigned c = atomicAdd(&g_count, 1u);
        is_last = (c == (unsigned)(gridDim.x - 1));
    }
    __syncthreads();

    // ---- last block: deterministic fixed-order final reduction ----
    if (is_last) {
        __threadfence();                      // see all g_part stores
        __shared__ double sd[BLK];
        double s = 0.0;
        for (int i = t; i < NBLOCKS; i += BLK)   // fixed index order
            s += g_part[i];
        sd[t] = s;
        __syncthreads();
        #pragma unroll
        for (int o = BLK / 2; o > 0; o >>= 1) {  // fixed-order tree
            if (t < o) sd[t] += sd[t + o];
            __syncthreads();
        }
        if (t == 0) {
            out[0] = (float)(sd[0] * (1.0 / 16384.0));
            g_count = 0;                      // reset for next replay
        }
    }
}

extern "C" void kernel_launch(void* const* d_in, const int* in_sizes, int n_in,
                              void* d_out, int out_size)
{
    const float* outputs   = (const float*)d_in[0];
    const float* gt_boxes  = (const float*)d_in[1];
    const int*   gt_labels = (const int*)  d_in[2];
    float* out = (float*)d_out;

    yolo_loss_kernel<<<NBLOCKS, BLK>>>(outputs, gt_boxes, gt_labels, out);
}

// round 10
// speedup vs baseline: 1.8279x; 1.0738x over previous
#include <cuda_runtime.h>
#include <math.h>

// YoloV1Loss_5136780886770 — R10
// R9 ncu: issue=54.7%, ALU=26.5%, FMA=19.9%, L1=41.7%, DRAM=38.8%, occ=57.3%
//  -> latency-bound, all pipes < 55%. Fix: ILP x2 (2 cells/thread) + shared
//     per-image GT preprocessing in smem.

#define NCELLS  (16384 * 49)
#define BLK     128
#define CPB     256                    // cells per block (2 per thread)
#define NBLOCKS (NCELLS / CPB)         // 3136 exactly, no tail
#define NVEC    ((CPB * 30) / 4)       // 1920 float4 per block
#define NIMG    7                      // max images spanned by 256 cells

__device__ double   g_part[NBLOCKS];
__device__ unsigned g_count = 0;       // returns to 0 every completed run (replay-safe)

// Per-cell loss. p = this cell's 30 staged channels; gt-derived data from smem.
__device__ __forceinline__ float cell_loss(
    const float*  __restrict__ p,
    const float4* __restrict__ gt4p,   // (gx1,gy1,gx2,gy2) per box
    const float*  __restrict__ garp,   // gt area per box
    const int*    __restrict__ glabp,  // labels per box
    const float*  __restrict__ gb)     // gt_boxes + img*32 (raw, for gt_sel)
{
    // channels -> registers via 15 LDS.64
    float ch[30];
    {
        const float2* p2 = (const float2*)p;   // 120B base, 8B-aligned
        #pragma unroll
        for (int i = 0; i < 15; i++) {
            float2 q = p2[i];
            ch[2*i] = q.x;  ch[2*i+1] = q.y;
        }
    }

    // predicted boxes (B=2)
    float x1[2], y1[2], x2[2], y2[2], area[2], conf[2];
    #pragma unroll
    for (int b = 0; b < 2; b++) {
        float cx = ch[b*5+0], cy = ch[b*5+1], w = ch[b*5+2], h = ch[b*5+3];
        conf[b] = ch[b*5+4];
        x1[b] = cx - 0.5f * w;  x2[b] = cx + 0.5f * w;
        y1[b] = cy - 0.5f * h;  y2[b] = cy + 0.5f * h;
        area[b] = w * h;
    }

    // IoU argmax via rational (inter, union+eps) cross-multiplication.
    // Carry (best_i, best_u, s1): bb at j_star == b-select bit of winning n.
    float best_i = 0.0f, best_u = 1.0f;
    bool  best_s1 = false;

    #pragma unroll
    for (int n = 0; n < 8; n++) {
        float4 G  = gt4p[n];           // LDS.128 broadcast (49 threads share)
        float  gA = garp[n];

        float iv[2], uv[2];
        #pragma unroll
        for (int b = 0; b < 2; b++) {
            float iw = fmaxf(fminf(x2[b], G.z) - fmaxf(x1[b], G.x), 0.0f);
            float ih = fmaxf(fminf(y2[b], G.w) - fmaxf(y1[b], G.y), 0.0f);
            float inter = iw * ih;
            iv[b] = inter;
            uv[b] = area[b] + gA - inter + 1e-6f;
        }
        bool  s1  = (iv[1] * uv[0] > iv[0] * uv[1]);   // tie -> b=0
        float m_i = s1 ? iv[1] : iv[0];
        float m_u = s1 ? uv[1] : uv[0];
        if (n == 0 || (m_i * best_u > best_i * m_u)) { // strict > == first occurrence
            best_i = m_i;  best_u = m_u;  best_s1 = s1;
        }
    }

    const int bb = best_s1 ? 1 : 0;
    const float best_iou = best_i / best_u;   // identical op/operands to reference

    // Faithful reference quirk: gt_sel = gt_boxes[img, best_b]
    float4 gs = __ldg((const float4*)(gb + bb * 4));

    float psx = best_s1 ? ch[5] : ch[0];
    float psy = best_s1 ? ch[6] : ch[1];
    float psw = best_s1 ? ch[7] : ch[2];
    float psh = best_s1 ? ch[8] : ch[3];

    float dx = psx - gs.x;
    float dy = psy - gs.y;
    float dw = sqrtf(psw) - sqrtf(gs.z);
    float dh = sqrtf(psh) - sqrtf(gs.w);
    float loc = 5.0f * (dx*dx + dy*dy + dw*dw + dh*dh);

    float dconf = (best_s1 ? conf[1] : conf[0]) - best_iou;
    float conf_obj = dconf * dconf;

    // cross-entropy: lse(cls) - mean_n cls[label_n]
    float mx = ch[10];
    #pragma unroll
    for (int c = 11; c < 30; c++) mx = fmaxf(mx, ch[c]);
    float se = 0.0f;
    #pragma unroll
    for (int c = 10; c < 30; c++) se += __expf(ch[c] - mx);
    float lse = mx + __logf(se);

    // dynamic gather stays in smem (register-indexing would spill to lmem)
    float acc = 0.0f;
    #pragma unroll
    for (int n = 0; n < 8; n++) acc += p[10 + glabp[n]];
    float ce = lse - acc * 0.125f;

    float noobj = 0.5f * (conf[0]*conf[0] + conf[1]*conf[1]);

    return (best_i > 0.0f) ? (loc + conf_obj + ce) : noobj;
}

__global__ void __launch_bounds__(BLK) yolo_loss_kernel(
    const float* __restrict__ outputs,
    const float* __restrict__ gt_boxes,
    const int*   __restrict__ gt_labels,
    float*       __restrict__ out)
{
    __shared__ float  sm[CPB * 30];        // staged cells (linear layout)
    __shared__ float4 gt4[NIMG * 8];       // per-image GT corners
    __shared__ float  gar[NIMG * 8];       // per-image GT areas
    __shared__ int    glab[NIMG * 8];      // per-image labels
    __shared__ float  wsum[BLK / 32];
    __shared__ bool   is_last;

    const int t    = threadIdx.x;
    const int base = blockIdx.x * CPB;
    const int img0 = base / 49;

    // ---- GT preprocessing: 56 entries, once per block ----
    if (t < NIMG * 8) {
        int li  = t >> 3, n = t & 7;
        int img = img0 + li;
        if (img < 16384) {
            float4 g = __ldg((const float4*)(gt_boxes + (size_t)img * 32 + n * 4));
            float hx = 0.5f * g.z, hy = 0.5f * g.w;
            gt4[t]  = make_float4(g.x - hx, g.y - hy, g.x + hx, g.y + hy);
            gar[t]  = g.z * g.w;
            glab[t] = __ldg(gt_labels + (size_t)img * 8 + n);
        }
    }

    // ---- staging: pure LDG.128 -> STS.128, 15 vec4 per thread ----
    {
        const float4* gsrc = (const float4*)(outputs + (size_t)base * 30);
        float4* sm4 = (float4*)sm;
        #pragma unroll
        for (int k = 0; k < NVEC / BLK; k++)     // 15, exact
            sm4[t + k * BLK] = gsrc[t + k * BLK];
    }
    __syncthreads();

    // ---- two independent cells per thread (ILP x2) ----
    const int cellA = base + t;
    const int cellB = base + t + BLK;
    const int imgA  = cellA / 49;
    const int imgB  = cellB / 49;
    const int liA   = imgA - img0;
    const int liB   = imgB - img0;

    float vA = cell_loss(sm + t * 30,
                         gt4 + liA * 8, gar + liA * 8, glab + liA * 8,
                         gt_boxes + (size_t)imgA * 32);
    float vB = cell_loss(sm + (t + BLK) * 30,
                         gt4 + liB * 8, gar + liB * 8, glab + liB * 8,
                         gt_boxes + (size_t)imgB * 32);
    float val = vA + vB;

    // ---- block reduction -> partial store ----
    #pragma unroll
    for (int o = 16; o > 0; o >>= 1)
        val += __shfl_down_sync(0xffffffffu, val, o);
    if ((t & 31) == 0) wsum[t >> 5] = val;
    __syncthreads();
    if (t == 0) {
        double s = 0.0;
        #pragma unroll
        for (int w = 0; w < BLK / 32; w++) s += (double)wsum[w];
        g_part[blockIdx.x] = s;
        __threadfence();
        unsigned c = atomicAdd(&g_count, 1u);
        is_last = (c == (unsigned)(gridDim.x - 1));
    }
    __syncthreads();

    // ---- last block: deterministic fixed-order final reduction ----
    if (is_last) {
        __threadfence();                      // see all g_part stores
        __shared__ double sd[BLK];
        double s = 0.0;
        for (int i = t; i < NBLOCKS; i += BLK)   // fixed index order
            s += g_part[i];
        sd[t] = s;
        __syncthreads();
        #pragma unroll
        for (int o = BLK / 2; o > 0; o >>= 1) {  // fixed-order tree
            if (t < o) sd[t] += sd[t + o];
            __syncthreads();
        }
        if (t == 0) {
            out[0] = (float)(sd[0] * (1.0 / 16384.0));
            g_count = 0;                      // reset for next replay
        }
    }
}

extern "C" void kernel_launch(void* const* d_in, const int* in_sizes, int n_in,
                              void* d_out, int out_size)
{
    const float* outputs   = (const float*)d_in[0];
    const float* gt_boxes  = (const float*)d_in[1];
    const int*   gt_labels = (const int*)  d_in[2];
    float* out = (float*)d_out;

    yolo_loss_kernel<<<NBLOCKS, BLK>>>(outputs, gt_boxes, gt_labels, out);
}